// round 16
// baseline (speedup 1.0000x reference)
#include <cuda_runtime.h>
#include <mma.h>
#include <cstdint>

using namespace nvcuda;

#define NN 100000
#define NNP 100096              // padded to multiple of 128 for unguarded wmma tiles
#define EE 1000000
#define DD 128
#define LL 2

// ---------------- scratch: accessed ONLY by symbol inside kernels ----------------
__device__ __align__(16) float g_h[NNP * DD];
__device__ __align__(16) float g_P[3 * NNP * DD];      // in / out / und projections
__device__ __align__(16) float g_acc[NN * DD];
__device__ __align__(16) float g_CWt[LL * DD * 384];   // combined weights [l][k][j384]

// -------- fused PE + init(l=0): h = x+pe ; acc = h + cst0 + C·biases ----------------
__global__ void k_pe_init(const float* __restrict__ x, const float* __restrict__ pe,
                          const float* __restrict__ cst,
                          const float* __restrict__ Cin, const float* __restrict__ Cout,
                          const float* __restrict__ Call,
                          const float* __restrict__ bmi, const float* __restrict__ bmo,
                          const float* __restrict__ bsi, const float* __restrict__ bso,
                          const float* __restrict__ bu) {
    int i4 = blockIdx.x * blockDim.x + threadIdx.x;   // float4 over NN*32
    if (i4 >= NN * 32) return;
    int n = i4 >> 5, d4 = i4 & 31;
    float4 xv = ((const float4*)x)[i4];
    float4 pv = ((const float4*)pe)[d4];
    float4 h = {xv.x + pv.x, xv.y + pv.y, xv.z + pv.z, xv.w + pv.w};
    ((float4*)g_h)[i4] = h;
    float4 c = ((const float4*)cst)[i4];
    float ci = Cin[n], co = Cout[n], ca = Call[n];
    float4 bi0 = ((const float4*)bmi)[d4];
    float4 bi1 = ((const float4*)bsi)[d4];
    float4 bo0 = ((const float4*)bmo)[d4];
    float4 bo1 = ((const float4*)bso)[d4];
    float4 bud = ((const float4*)bu)[d4];
    float4 r;
    r.x = h.x + c.x + ci * (bi0.x + bi1.x) + co * (bo0.x + bo1.x) + ca * bud.x;
    r.y = h.y + c.y + ci * (bi0.y + bi1.y) + co * (bo0.y + bo1.y) + ca * bud.y;
    r.z = h.z + c.z + ci * (bi0.z + bi1.z) + co * (bo0.z + bo1.z) + ca * bud.z;
    r.w = h.w + c.w + ci * (bi0.w + bi1.w) + co * (bo0.w + bo1.w) + ca * bud.w;
    ((float4*)g_acc)[i4] = r;
}

// -------- fused leaky + init(l=1) ---------------------------------------------------
__global__ void k_leaky_init(const float* __restrict__ cst,
                             const float* __restrict__ Cin, const float* __restrict__ Cout,
                             const float* __restrict__ Call,
                             const float* __restrict__ bmi, const float* __restrict__ bmo,
                             const float* __restrict__ bsi, const float* __restrict__ bso,
                             const float* __restrict__ bu) {
    int i4 = blockIdx.x * blockDim.x + threadIdx.x;
    if (i4 >= NN * 32) return;
    int n = i4 >> 5, d4 = i4 & 31;
    float4 a = ((const float4*)g_acc)[i4];
    float4 h;
    h.x = a.x > 0.f ? a.x : 0.01f * a.x;
    h.y = a.y > 0.f ? a.y : 0.01f * a.y;
    h.z = a.z > 0.f ? a.z : 0.01f * a.z;
    h.w = a.w > 0.f ? a.w : 0.01f * a.w;
    ((float4*)g_h)[i4] = h;
    float4 c = ((const float4*)cst)[i4];
    float ci = Cin[n], co = Cout[n], ca = Call[n];
    float4 bi0 = ((const float4*)bmi)[d4];
    float4 bi1 = ((const float4*)bsi)[d4];
    float4 bo0 = ((const float4*)bmo)[d4];
    float4 bo1 = ((const float4*)bso)[d4];
    float4 bud = ((const float4*)bu)[d4];
    float4 r;
    r.x = h.x + c.x + ci * (bi0.x + bi1.x) + co * (bo0.x + bo1.x) + ca * bud.x;
    r.y = h.y + c.y + ci * (bi0.y + bi1.y) + co * (bo0.y + bo1.y) + ca * bud.y;
    r.z = h.z + c.z + ci * (bi0.z + bi1.z) + co * (bo0.z + bo1.z) + ca * bud.z;
    r.w = h.w + c.w + ci * (bi0.w + bi1.w) + co * (bo0.w + bo1.w) + ca * bud.w;
    ((float4*)g_acc)[i4] = r;
}

// ---------------- combined weights: CWt[l][k][j] -----------------------------------
__global__ void k_wcomb(const float* __restrict__ Wmi, const float* __restrict__ Wmo,
                        const float* __restrict__ Ws,  const float* __restrict__ Wu) {
    int idx = blockIdx.x * blockDim.x + threadIdx.x;
    if (idx >= LL * 128 * 384) return;
    int l = idx / (128 * 384);
    int r = idx - l * (128 * 384);
    int k = r / 384;
    int j = r - k * 384;
    int lo = l * DD * DD;
    float v;
    if (j < 128)      v = Wmi[lo + j * DD + k] + Ws[lo + j * DD + k];
    else if (j < 256) v = Wmo[lo + (j - 128) * DD + k] + Ws[lo + (j - 128) * DD + k];
    else              v = Wu[lo + (j - 256) * DD + k];
    g_CWt[idx] = v;
}

// ---------------- tf32 wmma GEMM: P[slice][n][j] = sum_k h[n][k]*CWt[l][k][...] ------
// block: 256 threads (8 warps), 128x128 tile, K staged in smem chunks of 32.
// warp w: rows (w>>1)*32, cols (w&1)*64 -> 2x4 fragments of 16x16.
__global__ void k_gemm(int l, int slice) {
    __shared__ float As[128][40];   // [row][k], stride 40 (mult of 8)
    __shared__ float Bs[32][136];   // [k][j],  stride 136 (mult of 8)
    int tid = threadIdx.x;
    int rowBase = blockIdx.x * 128;   // rowBase+127 < NNP always
    int w = tid >> 5;
    int wr = w >> 1, wc = w & 1;
    const float* CWt = g_CWt + l * (128 * 384);

    wmma::fragment<wmma::accumulator, 16, 16, 8, float> c[2][4];
#pragma unroll
    for (int i = 0; i < 2; ++i)
#pragma unroll
        for (int j = 0; j < 4; ++j) wmma::fill_fragment(c[i][j], 0.f);

    for (int kc = 0; kc < 4; ++kc) {
        // stage A: 128 rows x 32 k (unguarded: g_h padded to NNP rows)
#pragma unroll
        for (int v = 0; v < 4; ++v) {
            int i4 = tid + v * 256;             // 0..1023
            int r = i4 >> 3, k4 = i4 & 7;
            float4 g = *(const float4*)&g_h[(size_t)(rowBase + r) * DD + kc * 32 + k4 * 4];
            *(float4*)&As[r][k4 * 4] = g;
        }
        // stage B: 32 k x 128 j
#pragma unroll
        for (int v = 0; v < 4; ++v) {
            int i4 = tid + v * 256;
            int kk = i4 >> 5, j4 = i4 & 31;
            float4 g = *(const float4*)&CWt[(size_t)(kc * 32 + kk) * 384 + slice * 128 + j4 * 4];
            *(float4*)&Bs[kk][j4 * 4] = g;
        }
        __syncthreads();

#pragma unroll
        for (int ks = 0; ks < 4; ++ks) {
            wmma::fragment<wmma::matrix_a, 16, 16, 8, wmma::precision::tf32, wmma::row_major> a[2];
            wmma::fragment<wmma::matrix_b, 16, 16, 8, wmma::precision::tf32, wmma::row_major> b[4];
#pragma unroll
            for (int i = 0; i < 2; ++i) {
                wmma::load_matrix_sync(a[i], &As[wr * 32 + i * 16][ks * 8], 40);
#pragma unroll
                for (int t = 0; t < a[i].num_elements; ++t)
                    a[i].x[t] = wmma::__float_to_tf32(a[i].x[t]);
            }
#pragma unroll
            for (int j = 0; j < 4; ++j) {
                wmma::load_matrix_sync(b[j], &Bs[ks * 8][wc * 64 + j * 16], 136);
#pragma unroll
                for (int t = 0; t < b[j].num_elements; ++t)
                    b[j].x[t] = wmma::__float_to_tf32(b[j].x[t]);
            }
#pragma unroll
            for (int i = 0; i < 2; ++i)
#pragma unroll
                for (int j = 0; j < 4; ++j)
                    wmma::mma_sync(c[i][j], a[i], b[j], c[i][j]);
        }
        __syncthreads();
    }

    float* Pout = g_P + (size_t)slice * NNP * DD;
#pragma unroll
    for (int i = 0; i < 2; ++i)
#pragma unroll
        for (int j = 0; j < 4; ++j) {
            int rr = rowBase + wr * 32 + i * 16;
            int cc = wc * 64 + j * 16;
            wmma::store_matrix_sync(&Pout[(size_t)rr * DD + cc], c[i][j], DD, wmma::mem_row_major);
        }
}

// ------- scatter, 4 edges per warp (MLP=4): acc[dst] += ew*C[dst]*P[slice][src] -----
__global__ void k_scatter(const int* __restrict__ ei, const float* __restrict__ ew,
                          const float* __restrict__ C, int l, int slice) {
    int gq = (blockIdx.x * blockDim.x + threadIdx.x) >> 5;   // warp index over EE/4
    int lane = threadIdx.x & 31;
    int e0 = gq * 4;
    if (e0 >= EE) return;
    const float* Pbase = g_P + (size_t)slice * NNP * DD;
    const float* Cl = C + l * NN;

    int src0 = ei[e0],      src1 = ei[e0 + 1],      src2 = ei[e0 + 2],      src3 = ei[e0 + 3];
    int dst0 = ei[EE + e0], dst1 = ei[EE + e0 + 1], dst2 = ei[EE + e0 + 2], dst3 = ei[EE + e0 + 3];
    float s0 = ew[e0]     * Cl[dst0];
    float s1 = ew[e0 + 1] * Cl[dst1];
    float s2 = ew[e0 + 2] * Cl[dst2];
    float s3 = ew[e0 + 3] * Cl[dst3];

    float4 p0 = *(const float4*)(Pbase + (size_t)src0 * DD + lane * 4);
    float4 p1 = *(const float4*)(Pbase + (size_t)src1 * DD + lane * 4);
    float4 p2 = *(const float4*)(Pbase + (size_t)src2 * DD + lane * 4);
    float4 p3 = *(const float4*)(Pbase + (size_t)src3 * DD + lane * 4);

    float* a0 = g_acc + (size_t)dst0 * DD + lane * 4;
    float* a1 = g_acc + (size_t)dst1 * DD + lane * 4;
    float* a2 = g_acc + (size_t)dst2 * DD + lane * 4;
    float* a3 = g_acc + (size_t)dst3 * DD + lane * 4;
    asm volatile("red.global.add.v4.f32 [%0], {%1,%2,%3,%4};"
                 :: "l"(a0), "f"(p0.x * s0), "f"(p0.y * s0), "f"(p0.z * s0), "f"(p0.w * s0) : "memory");
    asm volatile("red.global.add.v4.f32 [%0], {%1,%2,%3,%4};"
                 :: "l"(a1), "f"(p1.x * s1), "f"(p1.y * s1), "f"(p1.z * s1), "f"(p1.w * s1) : "memory");
    asm volatile("red.global.add.v4.f32 [%0], {%1,%2,%3,%4};"
                 :: "l"(a2), "f"(p2.x * s2), "f"(p2.y * s2), "f"(p2.z * s2), "f"(p2.w * s2) : "memory");
    asm volatile("red.global.add.v4.f32 [%0], {%1,%2,%3,%4};"
                 :: "l"(a3), "f"(p3.x * s3), "f"(p3.y * s3), "f"(p3.z * s3), "f"(p3.w * s3) : "memory");
}

// ---------------- decoder: warp per node, smem-transposed weights -------------------
__global__ void k_dec(const float* __restrict__ Wd1, const float* __restrict__ bd1,
                      const float* __restrict__ Wd2, const float* __restrict__ bd2,
                      float* __restrict__ out, int out_size) {
    __shared__ float sW1t[128 * 64];   // [k][j]
    __shared__ float sW2t[64 * 64];    // [k][j]
    int tid = threadIdx.x;
    for (int idx = tid; idx < 128 * 64; idx += 256) {
        int j = idx >> 7, k = idx & 127;
        sW1t[k * 64 + j] = Wd1[idx];
    }
    for (int idx = tid; idx < 64 * 64; idx += 256) {
        int j = idx >> 6, k = idx & 63;
        sW2t[k * 64 + j] = Wd2[idx];
    }
    __syncthreads();

    int w = tid >> 5, j = tid & 31;
    float b1a = bd1[j], b1b = bd1[j + 32];
    float b2a = bd2[j], b2b = bd2[j + 32];

#pragma unroll 1
    for (int i = 0; i < 8; ++i) {
        int n = blockIdx.x * 64 + i * 8 + w;
        if (n >= NN) break;
        const float* accp = g_acc + (size_t)n * DD;
        float hr[4];
#pragma unroll
        for (int q = 0; q < 4; ++q) {
            float v = accp[q * 32 + j];
            hr[q] = v > 0.f ? v : 0.01f * v;
        }
        float z0 = b1a, z1 = b1b;
#pragma unroll 4
        for (int k = 0; k < 128; ++k) {
            float hk = __shfl_sync(0xffffffffu, hr[k >> 5], k & 31);
            z0 = fmaf(sW1t[k * 64 + j], hk, z0);
            z1 = fmaf(sW1t[k * 64 + 32 + j], hk, z1);
        }
        z0 = fmaxf(z0, 0.f);
        z1 = fmaxf(z1, 0.f);
        float l0 = b2a, l1 = b2b;
#pragma unroll 4
        for (int k = 0; k < 64; ++k) {
            float zk = __shfl_sync(0xffffffffu, (k < 32) ? z0 : z1, k & 31);
            l0 = fmaf(sW2t[k * 64 + j], zk, l0);
            l1 = fmaf(sW2t[k * 64 + 32 + j], zk, l1);
        }
        float m = fmaxf(l0, l1);
#pragma unroll
        for (int off = 16; off; off >>= 1) m = fmaxf(m, __shfl_xor_sync(0xffffffffu, m, off));
        float s = expf(l0 - m) + expf(l1 - m);
#pragma unroll
        for (int off = 16; off; off >>= 1) s += __shfl_xor_sync(0xffffffffu, s, off);
        float lse = m + logf(s);
        int oi = n * 64 + j;
        if (oi < out_size) out[oi] = l0 - lse;
        if (oi + 32 < out_size) out[oi + 32] = l1 - lse;

        float ss = hr[0] * hr[0] + hr[1] * hr[1] + hr[2] * hr[2] + hr[3] * hr[3];
#pragma unroll
        for (int off = 16; off; off >>= 1) ss += __shfl_xor_sync(0xffffffffu, ss, off);
        float inv = 1.0f / fmaxf(sqrtf(ss), 1e-12f);
#pragma unroll
        for (int q = 0; q < 4; ++q) {
            int eo = NN * 64 + n * DD + q * 32 + j;
            if (eo < out_size) out[eo] = hr[q] * inv;
        }
    }
}

// ---------------- launch: NO device-global symbols referenced here -------------------
extern "C" void kernel_launch(void* const* d_in, const int* in_sizes, int n_in,
                              void* d_out, int out_size) {
    const float* x      = (const float*)d_in[0];
    const int*   ei_in  = (const int*)  d_in[1];
    const float* ew_in  = (const float*)d_in[2];
    const int*   ei_out = (const int*)  d_in[3];
    const float* ew_out = (const float*)d_in[4];
    const int*   ei_und = (const int*)  d_in[5];
    const float* ew_und = (const float*)d_in[6];
    const float* pe     = (const float*)d_in[7];
    const float* Wmi    = (const float*)d_in[8];
    const float* Wmo    = (const float*)d_in[9];
    const float* Ws     = (const float*)d_in[10];
    const float* Wu     = (const float*)d_in[11];
    const float* bmi    = (const float*)d_in[12];
    const float* bmo    = (const float*)d_in[13];
    const float* bsi    = (const float*)d_in[14];
    const float* bso    = (const float*)d_in[15];
    const float* bu     = (const float*)d_in[16];
    const float* Cin    = (const float*)d_in[17];
    const float* Cout   = (const float*)d_in[18];
    const float* Call   = (const float*)d_in[19];
    const float* cst    = (const float*)d_in[20];
    const float* Wd1    = (const float*)d_in[21];
    const float* bd1    = (const float*)d_in[22];
    const float* Wd2    = (const float*)d_in[23];
    const float* bd2    = (const float*)d_in[24];
    float* out = (float*)d_out;

    const int ew_blocks = (NN * 32 + 255) / 256;        // float4 elementwise
    const int sc_blocks = ((EE / 4) * 32 + 255) / 256;  // warp per 4 edges
    const int gemm_blocks = NNP / 128;                  // 782

    // #1, #2, #3
    k_pe_init<<<ew_blocks, 256>>>(x, pe, cst, Cin, Cout, Call, bmi, bmo, bsi, bso, bu);
    k_wcomb<<<(LL * 128 * 384 + 255) / 256, 256>>>(Wmi, Wmo, Ws, Wu);
    k_gemm<<<gemm_blocks, 256>>>(0, 0);
    // #4 (ncu-profiled slot): GEMM slice
    k_gemm<<<gemm_blocks, 256>>>(0, 1);
    k_gemm<<<gemm_blocks, 256>>>(0, 2);
    // scatters layer 0
    k_scatter<<<sc_blocks, 256>>>(ei_in,  ew_in,  Cin,  0, 0);
    k_scatter<<<sc_blocks, 256>>>(ei_out, ew_out, Cout, 0, 1);
    k_scatter<<<sc_blocks, 256>>>(ei_und, ew_und, Call, 0, 2);
    // layer 1
    k_leaky_init<<<ew_blocks, 256>>>(cst + (size_t)NN * DD, Cin + NN, Cout + NN, Call + NN,
                                     bmi + DD, bmo + DD, bsi + DD, bso + DD, bu + DD);
    k_gemm<<<gemm_blocks, 256>>>(1, 0);
    k_gemm<<<gemm_blocks, 256>>>(1, 1);
    k_gemm<<<gemm_blocks, 256>>>(1, 2);
    k_scatter<<<sc_blocks, 256>>>(ei_in,  ew_in,  Cin,  1, 0);
    k_scatter<<<sc_blocks, 256>>>(ei_out, ew_out, Cout, 1, 1);
    k_scatter<<<sc_blocks, 256>>>(ei_und, ew_und, Call, 1, 2);
    // decoder (final leaky fused in)
    k_dec<<<(NN + 63) / 64, 256>>>(Wd1, bd1, Wd2, bd2, out, out_size);
}

// round 17
// speedup vs baseline: 1.1265x; 1.1265x over previous
#include <cuda_runtime.h>
#include <mma.h>
#include <cstdint>

using namespace nvcuda;

#define NN 100000
#define NNP 100096              // padded to multiple of 128 for unguarded wmma tiles
#define EE 1000000
#define DD 128
#define LL 2

// ---------------- scratch: accessed ONLY by symbol inside kernels ----------------
__device__ __align__(16) float g_h[NNP * DD];
__device__ __align__(16) float g_P[3 * NNP * DD];      // in / out / und projections
__device__ __align__(16) float g_acc[NN * DD];
__device__ __align__(16) float g_CWt[LL * DD * 384];   // combined weights [l][k][j384]

// -------- fused PE + init(l=0) -------------------------------------------------------
__global__ void k_pe_init(const float* __restrict__ x, const float* __restrict__ pe,
                          const float* __restrict__ cst,
                          const float* __restrict__ Cin, const float* __restrict__ Cout,
                          const float* __restrict__ Call,
                          const float* __restrict__ bmi, const float* __restrict__ bmo,
                          const float* __restrict__ bsi, const float* __restrict__ bso,
                          const float* __restrict__ bu) {
    int i4 = blockIdx.x * blockDim.x + threadIdx.x;   // float4 over NN*32
    if (i4 >= NN * 32) return;
    int n = i4 >> 5, d4 = i4 & 31;
    float4 xv = ((const float4*)x)[i4];
    float4 pv = ((const float4*)pe)[d4];
    float4 h = {xv.x + pv.x, xv.y + pv.y, xv.z + pv.z, xv.w + pv.w};
    ((float4*)g_h)[i4] = h;
    float4 c = ((const float4*)cst)[i4];
    float ci = Cin[n], co = Cout[n], ca = Call[n];
    float4 bi0 = ((const float4*)bmi)[d4];
    float4 bi1 = ((const float4*)bsi)[d4];
    float4 bo0 = ((const float4*)bmo)[d4];
    float4 bo1 = ((const float4*)bso)[d4];
    float4 bud = ((const float4*)bu)[d4];
    float4 r;
    r.x = h.x + c.x + ci * (bi0.x + bi1.x) + co * (bo0.x + bo1.x) + ca * bud.x;
    r.y = h.y + c.y + ci * (bi0.y + bi1.y) + co * (bo0.y + bo1.y) + ca * bud.y;
    r.z = h.z + c.z + ci * (bi0.z + bi1.z) + co * (bo0.z + bo1.z) + ca * bud.z;
    r.w = h.w + c.w + ci * (bi0.w + bi1.w) + co * (bo0.w + bo1.w) + ca * bud.w;
    ((float4*)g_acc)[i4] = r;
}

// -------- fused leaky + init(l=1) ---------------------------------------------------
__global__ void k_leaky_init(const float* __restrict__ cst,
                             const float* __restrict__ Cin, const float* __restrict__ Cout,
                             const float* __restrict__ Call,
                             const float* __restrict__ bmi, const float* __restrict__ bmo,
                             const float* __restrict__ bsi, const float* __restrict__ bso,
                             const float* __restrict__ bu) {
    int i4 = blockIdx.x * blockDim.x + threadIdx.x;
    if (i4 >= NN * 32) return;
    int n = i4 >> 5, d4 = i4 & 31;
    float4 a = ((const float4*)g_acc)[i4];
    float4 h;
    h.x = a.x > 0.f ? a.x : 0.01f * a.x;
    h.y = a.y > 0.f ? a.y : 0.01f * a.y;
    h.z = a.z > 0.f ? a.z : 0.01f * a.z;
    h.w = a.w > 0.f ? a.w : 0.01f * a.w;
    ((float4*)g_h)[i4] = h;
    float4 c = ((const float4*)cst)[i4];
    float ci = Cin[n], co = Cout[n], ca = Call[n];
    float4 bi0 = ((const float4*)bmi)[d4];
    float4 bi1 = ((const float4*)bsi)[d4];
    float4 bo0 = ((const float4*)bmo)[d4];
    float4 bo1 = ((const float4*)bso)[d4];
    float4 bud = ((const float4*)bu)[d4];
    float4 r;
    r.x = h.x + c.x + ci * (bi0.x + bi1.x) + co * (bo0.x + bo1.x) + ca * bud.x;
    r.y = h.y + c.y + ci * (bi0.y + bi1.y) + co * (bo0.y + bo1.y) + ca * bud.y;
    r.z = h.z + c.z + ci * (bi0.z + bi1.z) + co * (bo0.z + bo1.z) + ca * bud.z;
    r.w = h.w + c.w + ci * (bi0.w + bi1.w) + co * (bo0.w + bo1.w) + ca * bud.w;
    ((float4*)g_acc)[i4] = r;
}

// ---------------- combined weights: CWt[l][k][j] -----------------------------------
__global__ void k_wcomb(const float* __restrict__ Wmi, const float* __restrict__ Wmo,
                        const float* __restrict__ Ws,  const float* __restrict__ Wu) {
    int idx = blockIdx.x * blockDim.x + threadIdx.x;
    if (idx >= LL * 128 * 384) return;
    int l = idx / (128 * 384);
    int r = idx - l * (128 * 384);
    int k = r / 384;
    int j = r - k * 384;
    int lo = l * DD * DD;
    float v;
    if (j < 128)      v = Wmi[lo + j * DD + k] + Ws[lo + j * DD + k];
    else if (j < 256) v = Wmo[lo + (j - 128) * DD + k] + Ws[lo + (j - 128) * DD + k];
    else              v = Wu[lo + (j - 256) * DD + k];
    g_CWt[idx] = v;
}

// ---------------- tf32 wmma GEMM, tf32 conversion at staging -------------------------
// grid: (rows/128, 3 slices); block 256 threads (8 warps); K staged in chunks of 32.
__global__ void __launch_bounds__(256, 2) k_gemm(int l, int rowOff) {
    __shared__ float As[128][40];   // [row][k], tf32-rounded
    __shared__ float Bs[32][136];   // [k][j],  tf32-rounded
    int tid = threadIdx.x;
    int slice = blockIdx.y;
    int rowBase = rowOff + blockIdx.x * 128;   // rowBase+127 < NNP always
    int w = tid >> 5;
    int wr = w >> 1, wc = w & 1;
    const float* CWt = g_CWt + l * (128 * 384);

    wmma::fragment<wmma::accumulator, 16, 16, 8, float> c[2][4];
#pragma unroll
    for (int i = 0; i < 2; ++i)
#pragma unroll
        for (int j = 0; j < 4; ++j) wmma::fill_fragment(c[i][j], 0.f);

    for (int kc = 0; kc < 4; ++kc) {
#pragma unroll
        for (int v = 0; v < 4; ++v) {
            int i4 = tid + v * 256;             // 0..1023
            int r = i4 >> 3, k4 = i4 & 7;
            float4 g = *(const float4*)&g_h[(size_t)(rowBase + r) * DD + kc * 32 + k4 * 4];
            As[r][k4 * 4 + 0] = wmma::__float_to_tf32(g.x);
            As[r][k4 * 4 + 1] = wmma::__float_to_tf32(g.y);
            As[r][k4 * 4 + 2] = wmma::__float_to_tf32(g.z);
            As[r][k4 * 4 + 3] = wmma::__float_to_tf32(g.w);
        }
#pragma unroll
        for (int v = 0; v < 4; ++v) {
            int i4 = tid + v * 256;
            int kk = i4 >> 5, j4 = i4 & 31;
            float4 g = *(const float4*)&CWt[(size_t)(kc * 32 + kk) * 384 + slice * 128 + j4 * 4];
            Bs[kk][j4 * 4 + 0] = wmma::__float_to_tf32(g.x);
            Bs[kk][j4 * 4 + 1] = wmma::__float_to_tf32(g.y);
            Bs[kk][j4 * 4 + 2] = wmma::__float_to_tf32(g.z);
            Bs[kk][j4 * 4 + 3] = wmma::__float_to_tf32(g.w);
        }
        __syncthreads();

#pragma unroll
        for (int ks = 0; ks < 4; ++ks) {
            wmma::fragment<wmma::matrix_a, 16, 16, 8, wmma::precision::tf32, wmma::row_major> a[2];
            wmma::fragment<wmma::matrix_b, 16, 16, 8, wmma::precision::tf32, wmma::row_major> b[4];
#pragma unroll
            for (int i = 0; i < 2; ++i)
                wmma::load_matrix_sync(a[i], &As[wr * 32 + i * 16][ks * 8], 40);
#pragma unroll
            for (int j = 0; j < 4; ++j)
                wmma::load_matrix_sync(b[j], &Bs[ks * 8][wc * 64 + j * 16], 136);
#pragma unroll
            for (int i = 0; i < 2; ++i)
#pragma unroll
                for (int j = 0; j < 4; ++j)
                    wmma::mma_sync(c[i][j], a[i], b[j], c[i][j]);
        }
        __syncthreads();
    }

    float* Pout = g_P + (size_t)slice * NNP * DD;
#pragma unroll
    for (int i = 0; i < 2; ++i)
#pragma unroll
        for (int j = 0; j < 4; ++j) {
            int rr = rowBase + wr * 32 + i * 16;
            int cc = wc * 64 + j * 16;
            wmma::store_matrix_sync(&Pout[(size_t)rr * DD + cc], c[i][j], DD, wmma::mem_row_major);
        }
}

// ------- scatter, 4 edges per warp (MLP=4) ------------------------------------------
__global__ void k_scatter(const int* __restrict__ ei, const float* __restrict__ ew,
                          const float* __restrict__ C, int l, int slice) {
    int gq = (blockIdx.x * blockDim.x + threadIdx.x) >> 5;   // warp index over EE/4
    int lane = threadIdx.x & 31;
    int e0 = gq * 4;
    if (e0 >= EE) return;
    const float* Pbase = g_P + (size_t)slice * NNP * DD;
    const float* Cl = C + l * NN;

    int src0 = ei[e0],      src1 = ei[e0 + 1],      src2 = ei[e0 + 2],      src3 = ei[e0 + 3];
    int dst0 = ei[EE + e0], dst1 = ei[EE + e0 + 1], dst2 = ei[EE + e0 + 2], dst3 = ei[EE + e0 + 3];
    float s0 = ew[e0]     * Cl[dst0];
    float s1 = ew[e0 + 1] * Cl[dst1];
    float s2 = ew[e0 + 2] * Cl[dst2];
    float s3 = ew[e0 + 3] * Cl[dst3];

    float4 p0 = *(const float4*)(Pbase + (size_t)src0 * DD + lane * 4);
    float4 p1 = *(const float4*)(Pbase + (size_t)src1 * DD + lane * 4);
    float4 p2 = *(const float4*)(Pbase + (size_t)src2 * DD + lane * 4);
    float4 p3 = *(const float4*)(Pbase + (size_t)src3 * DD + lane * 4);

    float* a0 = g_acc + (size_t)dst0 * DD + lane * 4;
    float* a1 = g_acc + (size_t)dst1 * DD + lane * 4;
    float* a2 = g_acc + (size_t)dst2 * DD + lane * 4;
    float* a3 = g_acc + (size_t)dst3 * DD + lane * 4;
    asm volatile("red.global.add.v4.f32 [%0], {%1,%2,%3,%4};"
                 :: "l"(a0), "f"(p0.x * s0), "f"(p0.y * s0), "f"(p0.z * s0), "f"(p0.w * s0) : "memory");
    asm volatile("red.global.add.v4.f32 [%0], {%1,%2,%3,%4};"
                 :: "l"(a1), "f"(p1.x * s1), "f"(p1.y * s1), "f"(p1.z * s1), "f"(p1.w * s1) : "memory");
    asm volatile("red.global.add.v4.f32 [%0], {%1,%2,%3,%4};"
                 :: "l"(a2), "f"(p2.x * s2), "f"(p2.y * s2), "f"(p2.z * s2), "f"(p2.w * s2) : "memory");
    asm volatile("red.global.add.v4.f32 [%0], {%1,%2,%3,%4};"
                 :: "l"(a3), "f"(p3.x * s3), "f"(p3.y * s3), "f"(p3.z * s3), "f"(p3.w * s3) : "memory");
}

// ---------------- decoder: warp per node, smem-transposed weights -------------------
__global__ void k_dec(const float* __restrict__ Wd1, const float* __restrict__ bd1,
                      const float* __restrict__ Wd2, const float* __restrict__ bd2,
                      float* __restrict__ out, int out_size) {
    __shared__ float sW1t[128 * 64];   // [k][j]
    __shared__ float sW2t[64 * 64];    // [k][j]
    int tid = threadIdx.x;
    for (int idx = tid; idx < 128 * 64; idx += 256) {
        int j = idx >> 7, k = idx & 127;
        sW1t[k * 64 + j] = Wd1[idx];
    }
    for (int idx = tid; idx < 64 * 64; idx += 256) {
        int j = idx >> 6, k = idx & 63;
        sW2t[k * 64 + j] = Wd2[idx];
    }
    __syncthreads();

    int w = tid >> 5, j = tid & 31;
    float b1a = bd1[j], b1b = bd1[j + 32];
    float b2a = bd2[j], b2b = bd2[j + 32];

#pragma unroll 1
    for (int i = 0; i < 8; ++i) {
        int n = blockIdx.x * 64 + i * 8 + w;
        if (n >= NN) break;
        const float* accp = g_acc + (size_t)n * DD;
        float hr[4];
#pragma unroll
        for (int q = 0; q < 4; ++q) {
            float v = accp[q * 32 + j];
            hr[q] = v > 0.f ? v : 0.01f * v;
        }
        float z0 = b1a, z1 = b1b;
#pragma unroll 4
        for (int k = 0; k < 128; ++k) {
            float hk = __shfl_sync(0xffffffffu, hr[k >> 5], k & 31);
            z0 = fmaf(sW1t[k * 64 + j], hk, z0);
            z1 = fmaf(sW1t[k * 64 + 32 + j], hk, z1);
        }
        z0 = fmaxf(z0, 0.f);
        z1 = fmaxf(z1, 0.f);
        float l0 = b2a, l1 = b2b;
#pragma unroll 4
        for (int k = 0; k < 64; ++k) {
            float zk = __shfl_sync(0xffffffffu, (k < 32) ? z0 : z1, k & 31);
            l0 = fmaf(sW2t[k * 64 + j], zk, l0);
            l1 = fmaf(sW2t[k * 64 + 32 + j], zk, l1);
        }
        float m = fmaxf(l0, l1);
#pragma unroll
        for (int off = 16; off; off >>= 1) m = fmaxf(m, __shfl_xor_sync(0xffffffffu, m, off));
        float s = expf(l0 - m) + expf(l1 - m);
#pragma unroll
        for (int off = 16; off; off >>= 1) s += __shfl_xor_sync(0xffffffffu, s, off);
        float lse = m + logf(s);
        int oi = n * 64 + j;
        if (oi < out_size) out[oi] = l0 - lse;
        if (oi + 32 < out_size) out[oi + 32] = l1 - lse;

        float ss = hr[0] * hr[0] + hr[1] * hr[1] + hr[2] * hr[2] + hr[3] * hr[3];
#pragma unroll
        for (int off = 16; off; off >>= 1) ss += __shfl_xor_sync(0xffffffffu, ss, off);
        float inv = 1.0f / fmaxf(sqrtf(ss), 1e-12f);
#pragma unroll
        for (int q = 0; q < 4; ++q) {
            int eo = NN * 64 + n * DD + q * 32 + j;
            if (eo < out_size) out[eo] = hr[q] * inv;
        }
    }
}

// ---------------- launch: NO device-global symbols referenced here -------------------
extern "C" void kernel_launch(void* const* d_in, const int* in_sizes, int n_in,
                              void* d_out, int out_size) {
    const float* x      = (const float*)d_in[0];
    const int*   ei_in  = (const int*)  d_in[1];
    const float* ew_in  = (const float*)d_in[2];
    const int*   ei_out = (const int*)  d_in[3];
    const float* ew_out = (const float*)d_in[4];
    const int*   ei_und = (const int*)  d_in[5];
    const float* ew_und = (const float*)d_in[6];
    const float* pe     = (const float*)d_in[7];
    const float* Wmi    = (const float*)d_in[8];
    const float* Wmo    = (const float*)d_in[9];
    const float* Ws     = (const float*)d_in[10];
    const float* Wu     = (const float*)d_in[11];
    const float* bmi    = (const float*)d_in[12];
    const float* bmo    = (const float*)d_in[13];
    const float* bsi    = (const float*)d_in[14];
    const float* bso    = (const float*)d_in[15];
    const float* bu     = (const float*)d_in[16];
    const float* Cin    = (const float*)d_in[17];
    const float* Cout   = (const float*)d_in[18];
    const float* Call   = (const float*)d_in[19];
    const float* cst    = (const float*)d_in[20];
    const float* Wd1    = (const float*)d_in[21];
    const float* bd1    = (const float*)d_in[22];
    const float* Wd2    = (const float*)d_in[23];
    const float* bd2    = (const float*)d_in[24];
    float* out = (float*)d_out;

    const int ew_blocks = (NN * 32 + 255) / 256;        // float4 elementwise
    const int sc_blocks = ((EE / 4) * 32 + 255) / 256;  // warp per 4 edges
    const int half1 = 50048;                            // 391 * 128
    const int g1 = half1 / 128;                         // 391
    const int g2 = (NNP - half1) / 128;                 // 391

    // #1, #2
    k_pe_init<<<ew_blocks, 256>>>(x, pe, cst, Cin, Cout, Call, bmi, bmo, bsi, bso, bu);
    k_wcomb<<<(LL * 128 * 384 + 255) / 256, 256>>>(Wmi, Wmo, Ws, Wu);
    // #3, #4 (slot #4 = ncu-profiled): GEMM row-halves, layer 0, all 3 slices each
    k_gemm<<<dim3(g1, 3), 256>>>(0, 0);
    k_gemm<<<dim3(g2, 3), 256>>>(0, half1);
    // scatters layer 0
    k_scatter<<<sc_blocks, 256>>>(ei_in,  ew_in,  Cin,  0, 0);
    k_scatter<<<sc_blocks, 256>>>(ei_out, ew_out, Cout, 0, 1);
    k_scatter<<<sc_blocks, 256>>>(ei_und, ew_und, Call, 0, 2);
    // layer 1
    k_leaky_init<<<ew_blocks, 256>>>(cst + (size_t)NN * DD, Cin + NN, Cout + NN, Call + NN,
                                     bmi + DD, bmo + DD, bsi + DD, bso + DD, bu + DD);
    k_gemm<<<dim3(g1, 3), 256>>>(1, 0);
    k_gemm<<<dim3(g2, 3), 256>>>(1, half1);
    k_scatter<<<sc_blocks, 256>>>(ei_in,  ew_in,  Cin,  1, 0);
    k_scatter<<<sc_blocks, 256>>>(ei_out, ew_out, Cout, 1, 1);
    k_scatter<<<sc_blocks, 256>>>(ei_und, ew_und, Call, 1, 2);
    // decoder (final leaky fused in)
    k_dec<<<(NN + 63) / 64, 256>>>(Wd1, bd1, Wd2, bd2, out, out_size);
}